// round 14
// baseline (speedup 1.0000x reference)
#include <cuda_runtime.h>

// SiluAndMul: x [M, 2N] fp32 -> out [M, N] fp32, out = silu(x[:, :N]) * x[:, N:]
// M = 16384, N = 11008. Pure HBM-bound: 2.164 GB/launch.
//
// R14: REPRODUCTION of R13's block=192 (timed session-best 298.1us, n=1).
// Block-size curve (profiled DRAM% / timed us):
//   64:  74.6% / 360.1   (CTA-refill starvation)
//   128: 91.4% / 300.3, 299.2   (profiled best: 294.5us, 7245 GB/s)
//   192: 90.9% / 298.1   <- timed best, reproducing now
//   256: 90.0% / 299.5, 299.6, 299.5, 299.8
// If 298.x reproduces, block=192 is final (better in warm-L2 replay regime);
// if it regresses to >=299, revert to block=128 on profiled evidence.
// All other axes closed: plain ld/st, 1 float4/thread, 2D grid.

static constexpr int M = 16384;
static constexpr int N = 11008;         // output cols
static constexpr int TWO_N = 2 * N;     // input row stride (floats)
static constexpr int N4 = N / 4;        // 2752 float4 per output row
static constexpr int BLOCK = 192;

__global__ __launch_bounds__(BLOCK) void silu_and_mul_kernel(
    const float* __restrict__ x, float* __restrict__ out)
{
    const int col4 = blockIdx.x * BLOCK + threadIdx.x;  // float4 column index
    if (col4 >= N4) return;
    const long long row = blockIdx.y;

    const float4* gate4 = reinterpret_cast<const float4*>(x + row * TWO_N);
    const float4* up4   = reinterpret_cast<const float4*>(x + row * TWO_N + N);
    float4* out4        = reinterpret_cast<float4*>(out + row * (long long)N);

    float4 g = gate4[col4];
    float4 u = up4[col4];

    float4 r;
    r.x = (g.x * __frcp_rn(1.0f + __expf(-g.x))) * u.x;
    r.y = (g.y * __frcp_rn(1.0f + __expf(-g.y))) * u.y;
    r.z = (g.z * __frcp_rn(1.0f + __expf(-g.z))) * u.z;
    r.w = (g.w * __frcp_rn(1.0f + __expf(-g.w))) * u.w;

    out4[col4] = r;
}

extern "C" void kernel_launch(void* const* d_in, const int* in_sizes, int n_in,
                              void* d_out, int out_size)
{
    const float* x = (const float*)d_in[0];
    float* out = (float*)d_out;

    dim3 block(BLOCK);
    dim3 grid((N4 + BLOCK - 1) / BLOCK, M);   // (15, 16384)
    silu_and_mul_kernel<<<grid, block>>>(x, out);
}